// round 5
// baseline (speedup 1.0000x reference)
#include <cuda_runtime.h>
#include <cuda_bf16.h>
#include <cuda_fp16.h>

#define NB 8
#define NT 256   // T_en == T_de
#define ND 256
#define NU 256

// Scratch (device globals: no allocation allowed in kernel_launch)
__device__ __half d_aeT_h[NB * NU * NT];  // aeT[b][u][e] fp16 (e contiguous)
__device__ float  d_ad   [NB * NT * NU];  // ad [b][t][u] fp32
__device__ __half d_en_h [NB * NT * ND];  // en[b][e][d] fp16 (d contiguous)

// ---------------------------------------------------------------------------
// Fused GEMM: att_en (fp16 transposed store) and att_de (fp32).
// ---------------------------------------------------------------------------
__global__ __launch_bounds__(256) void gemm_kernel(const float* __restrict__ en,
                                                   const float* __restrict__ de,
                                                   const float* __restrict__ w_en,
                                                   const float* __restrict__ w_de)
{
    const int z     = blockIdx.z;
    const int b     = z >> 1;
    const int which = z & 1;

    const float* A  = which ? (de + b * NT * ND) : (en + b * NT * ND);
    const float* Bm = which ? w_de : w_en;

    const int m0 = blockIdx.y * 64;
    const int n0 = blockIdx.x * 64;

    __shared__ float As[16][68];
    __shared__ float Bs[16][64];

    const int tid   = threadIdx.x;
    const int a_row = tid >> 2;
    const int a_k4  = (tid & 3) << 2;
    const int b_k   = tid >> 4;
    const int b_n4  = (tid & 15) << 2;
    const int tm    = tid >> 4;
    const int tn    = tid & 15;

    const bool emit_en = (which == 0) && (n0 == 0);

    float acc[4][4];
#pragma unroll
    for (int i = 0; i < 4; i++)
#pragma unroll
        for (int j = 0; j < 4; j++) acc[i][j] = 0.f;

    for (int k0 = 0; k0 < 256; k0 += 16) {
        float4 av = *(const float4*)(A  + (m0 + a_row) * 256 + k0 + a_k4);
        float4 bv = *(const float4*)(Bm + (k0 + b_k)   * 256 + n0 + b_n4);
        if (emit_en) {
            __half2 lo = __floats2half2_rn(av.x, av.y);
            __half2 hi = __floats2half2_rn(av.z, av.w);
            uint2 o;
            o.x = *(unsigned*)&lo;
            o.y = *(unsigned*)&hi;
            *(uint2*)(d_en_h + b * NT * ND + (m0 + a_row) * ND + k0 + a_k4) = o;
        }
        __syncthreads();
        As[a_k4 + 0][a_row] = av.x;
        As[a_k4 + 1][a_row] = av.y;
        As[a_k4 + 2][a_row] = av.z;
        As[a_k4 + 3][a_row] = av.w;
        *(float4*)&Bs[b_k][b_n4] = bv;
        __syncthreads();
#pragma unroll
        for (int k = 0; k < 16; k++) {
            float4 a4 = *(const float4*)&As[k][tm << 2];
            float4 b4 = *(const float4*)&Bs[k][tn << 2];
            float ar[4] = {a4.x, a4.y, a4.z, a4.w};
            float br[4] = {b4.x, b4.y, b4.z, b4.w};
#pragma unroll
            for (int i = 0; i < 4; i++)
#pragma unroll
                for (int j = 0; j < 4; j++)
                    acc[i][j] = fmaf(ar[i], br[j], acc[i][j]);
        }
    }

    if (which == 0) {
        __half* dst = d_aeT_h + b * NU * NT;
#pragma unroll
        for (int j = 0; j < 4; j++) {
            int u = n0 + (tn << 2) + j;
            __half2 lo = __floats2half2_rn(acc[0][j], acc[1][j]);
            __half2 hi = __floats2half2_rn(acc[2][j], acc[3][j]);
            uint2 v;
            v.x = *(unsigned*)&lo;
            v.y = *(unsigned*)&hi;
            *(uint2*)(dst + u * NT + m0 + (tm << 2)) = v;
        }
    } else {
        float* dst = d_ad + b * NT * NU;
#pragma unroll
        for (int i = 0; i < 4; i++) {
            int t = m0 + (tm << 2) + i;
            float4 v = make_float4(acc[i][0], acc[i][1], acc[i][2], acc[i][3]);
            *(float4*)(dst + t * NU + n0 + (tn << 2)) = v;
        }
    }
}

// ---------------------------------------------------------------------------
// Fused tanh-score + softmax + context. One CTA = (b, 4 decoder rows),
// 512 threads in 2 groups: group g covers u (score) / e (context) range
// [128g, 128g+128). Doubles warp parallelism vs one-group version.
// ---------------------------------------------------------------------------
#define UT 16                        // u (or e) rows per staged tile
#define TILE_HALFS (UT * 256)        // 4096 halfs = 8KB
#define NTILES 8                     // 128 rows per group / 16

__device__ __forceinline__ void stage8k(unsigned sbase, const __half* g, int t256)
{
    unsigned s = sbase + t256 * 32;
    const char* gp = (const char*)g + t256 * 32;
    asm volatile("cp.async.cg.shared.global [%0], [%1], 16;\n"
                 "cp.async.cg.shared.global [%2], [%3], 16;\n"
                 "cp.async.commit_group;\n"
                 :: "r"(s), "l"(gp), "r"(s + 16), "l"(gp + 16) : "memory");
}

__global__ __launch_bounds__(512, 3) void attn_kernel(const float* __restrict__ de,
                                                      const float* __restrict__ nu,
                                                      float* __restrict__ out)
{
    const int b    = blockIdx.x >> 6;          // 8 b * 64 groups
    const int t0   = (blockIdx.x & 63) << 2;   // 4 decoder rows per CTA
    const int tid  = threadIdx.x;
    const int g    = tid >> 8;                 // group 0/1
    const int e    = tid & 255;                // e (score) / d (context)
    const int wid  = tid >> 5;

    __shared__ __half buf[2][2][TILE_HALFS];   // [group][stage] 4x8KB
    __shared__ uint4  pk[256];                 // {ad01, ad23, nu2, pad} per u
    __shared__ float4 partA[256];              // g0 score partials -> alpha4
    __shared__ float4 partB[256];              // g1 score partials -> ctx partials
    __shared__ float4 redM[16];
    __shared__ float4 redS[16];

    const unsigned sb[2] = {
        (unsigned)__cvta_generic_to_shared(&buf[g][0][0]),
        (unsigned)__cvta_generic_to_shared(&buf[g][1][0])
    };

    const __half* aeg = d_aeT_h + b * NU * NT + g * 128 * 256;  // group's u range
    const __half* eng = d_en_h  + b * NT * ND + g * 128 * 256;  // group's e range

    // prologue: stage ae tile 0; fill pk meanwhile
    stage8k(sb[0], aeg, e);
    if (tid < 256) {
        const float* ap = d_ad + (b * NT + t0) * NU + tid;
        __half2 ad01 = __floats2half2_rn(ap[0],      ap[NU]);
        __half2 ad23 = __floats2half2_rn(ap[2 * NU], ap[3 * NU]);
        __half2 nu2  = __float2half2_rn(nu[tid]);
        uint4 p;
        p.x = *(unsigned*)&ad01;
        p.y = *(unsigned*)&ad23;
        p.z = *(unsigned*)&nu2;
        p.w = 0;
        pk[tid] = p;
    }

    // ---- scores: 128 u per group, staged in 8 tiles of 16 ----
    float m0 = 0.f, m1 = 0.f, m2 = 0.f, m3 = 0.f;
    for (int t = 0; t < NTILES; ++t) {
        if (t < NTILES - 1) {
            stage8k(sb[(t + 1) & 1], aeg + (t + 1) * TILE_HALFS, e);
            asm volatile("cp.async.wait_group 1;" ::: "memory");
        } else {
            asm volatile("cp.async.wait_group 0;" ::: "memory");
        }
        __syncthreads();

        const __half* sa = &buf[g][t & 1][e];
        const int u0 = (g << 7) + t * UT;
        __half2 a01 = __float2half2_rn(0.f);
        __half2 a23 = __float2half2_rn(0.f);
#pragma unroll
        for (int k = 0; k < UT; k++) {
            __half  a  = sa[k << 8];            // LDS.16, conflict-free
            uint4   p  = pk[u0 + k];            // LDS.128 broadcast
            __half2 ah = __half2half2(a);
            __half2 c01 = __hadd2(ah, *(__half2*)&p.x);
            __half2 c23 = __hadd2(ah, *(__half2*)&p.y);
            unsigned t01, t23;
            asm("tanh.approx.f16x2 %0, %1;" : "=r"(t01) : "r"(*(unsigned*)&c01));
            asm("tanh.approx.f16x2 %0, %1;" : "=r"(t23) : "r"(*(unsigned*)&c23));
            a01 = __hfma2(*(__half2*)&t01, *(__half2*)&p.z, a01);
            a23 = __hfma2(*(__half2*)&t23, *(__half2*)&p.z, a23);
        }
        float2 f01 = __half22float2(a01);
        float2 f23 = __half22float2(a23);
        m0 += f01.x; m1 += f01.y; m2 += f23.x; m3 += f23.y;
        __syncthreads();
    }

    // prefetch en tile 0 for context — latency hides under softmax
    stage8k(sb[0], eng, e);

    // ---- cross-group reduce of score partials ----
    if (g == 0) partA[e] = make_float4(m0, m1, m2, m3);
    else        partB[e] = make_float4(m0, m1, m2, m3);
    __syncthreads();
    float4 pa = partA[e], pb = partB[e];
    float4 mu = make_float4(pa.x + pb.x, pa.y + pb.y, pa.z + pb.z, pa.w + pb.w);

    // ---- softmax over e, all 4 rows at once (both groups redundantly) ----
    float4 mx = mu;
#pragma unroll
    for (int o = 16; o; o >>= 1) {
        mx.x = fmaxf(mx.x, __shfl_xor_sync(0xffffffffu, mx.x, o));
        mx.y = fmaxf(mx.y, __shfl_xor_sync(0xffffffffu, mx.y, o));
        mx.z = fmaxf(mx.z, __shfl_xor_sync(0xffffffffu, mx.z, o));
        mx.w = fmaxf(mx.w, __shfl_xor_sync(0xffffffffu, mx.w, o));
    }
    if ((tid & 31) == 0) redM[wid] = mx;
    __syncthreads();
    mx = redM[0];
#pragma unroll
    for (int w = 1; w < 16; w++) {
        float4 r = redM[w];
        mx.x = fmaxf(mx.x, r.x); mx.y = fmaxf(mx.y, r.y);
        mx.z = fmaxf(mx.z, r.z); mx.w = fmaxf(mx.w, r.w);
    }
    float4 ex = make_float4(__expf(mu.x - mx.x), __expf(mu.y - mx.y),
                            __expf(mu.z - mx.z), __expf(mu.w - mx.w));
    float4 s = ex;
#pragma unroll
    for (int o = 16; o; o >>= 1) {
        s.x += __shfl_xor_sync(0xffffffffu, s.x, o);
        s.y += __shfl_xor_sync(0xffffffffu, s.y, o);
        s.z += __shfl_xor_sync(0xffffffffu, s.z, o);
        s.w += __shfl_xor_sync(0xffffffffu, s.w, o);
    }
    if ((tid & 31) == 0) redS[wid] = s;
    __syncthreads();
    s = redS[0];
#pragma unroll
    for (int w = 1; w < 8; w++) {       // group-0 warps cover all e exactly once
        float4 r = redS[w];
        s.x += r.x; s.y += r.y; s.z += r.z; s.w += r.w;
    }
    float4 al = make_float4(__fdividef(ex.x, s.x), __fdividef(ex.y, s.y),
                            __fdividef(ex.z, s.z), __fdividef(ex.w, s.w));
    if (g == 0) partA[e] = al;          // partA becomes alpha4
    __syncthreads();

    // ---- context: 128 e per group, staged tiles; thread = d ----
    const float* dep = de + (b * NT + t0) * ND + e;
    float de0 = dep[0], de1 = dep[ND], de2 = dep[2 * ND], de3 = dep[3 * ND];
    float o0 = 0.f, o1 = 0.f, o2 = 0.f, o3 = 0.f;
    for (int t = 0; t < NTILES; ++t) {
        if (t < NTILES - 1) {
            stage8k(sb[(t + 1) & 1], eng + (t + 1) * TILE_HALFS, e);
            asm volatile("cp.async.wait_group 1;" ::: "memory");
        } else {
            asm volatile("cp.async.wait_group 0;" ::: "memory");
        }
        __syncthreads();

        const __half* sv = &buf[g][t & 1][e];
        const int e0 = (g << 7) + t * UT;
#pragma unroll
        for (int k = 0; k < UT; k++) {
            float  v = __half2float(sv[k << 8]);
            float4 a = partA[e0 + k];           // alpha4 broadcast
            o0 = fmaf(a.x, v, o0);
            o1 = fmaf(a.y, v, o1);
            o2 = fmaf(a.z, v, o2);
            o3 = fmaf(a.w, v, o3);
        }
        __syncthreads();
    }

    // ---- cross-group reduce of context partials + store ----
    if (g == 1) partB[e] = make_float4(o0, o1, o2, o3);
    __syncthreads();
    if (g == 0) {
        float4 p = partB[e];
        float* op = out + (b * NT + t0) * ND + e;
        op[0]      = o0 + p.x + de0;
        op[ND]     = o1 + p.y + de1;
        op[2 * ND] = o2 + p.z + de2;
        op[3 * ND] = o3 + p.w + de3;
    }
}

extern "C" void kernel_launch(void* const* d_in, const int* in_sizes, int n_in,
                              void* d_out, int out_size)
{
    const float* en   = (const float*)d_in[0];   // (8,256,256)
    const float* de   = (const float*)d_in[1];   // (8,256,256)
    const float* w_en = (const float*)d_in[2];   // (256,256)
    const float* w_de = (const float*)d_in[3];   // (256,256)
    const float* nu   = (const float*)d_in[4];   // (256,1)
    float* out = (float*)d_out;                  // (8,256,256) fp32

    dim3 gg(4, 4, 16);
    gemm_kernel<<<gg, 256>>>(en, de, w_en, w_de);
    attn_kernel<<<NB * (NT / 4), 512>>>(de, nu, out);
}